// round 1
// baseline (speedup 1.0000x reference)
#include <cuda_runtime.h>
#include <math.h>

#define B_   2
#define N_   2048
#define D_   1024
#define H_   16
#define DK_  64
#define M_   (B_ * N_)   // 4096

// Scratch (allocation-free rule: __device__ globals)
__device__ float g_Q[B_ * H_ * N_ * DK_];   // 16 MB, head-major [b][h][n][dk]
__device__ float g_K[B_ * H_ * N_ * DK_];
__device__ float g_V[B_ * H_ * N_ * DK_];
__device__ float g_Y[M_ * D_];              // attention output, row-major [b*n][d]

// ---------------------------------------------------------------------------
// SGEMM: C[M=4096, N=1024] = X[4096,1024] @ W[1024,1024] + bias, fp32
// mode 0: write head-major (Q), mode 1: head-major * (1+alpha[row]) (K/V),
// mode 2: plain row-major (output projection)
// Tile 128x128x16, 256 threads, 8x8 per thread.
// ---------------------------------------------------------------------------
__global__ __launch_bounds__(256) void sgemm_kernel(
    const float* __restrict__ X, const float* __restrict__ W,
    const float* __restrict__ bvec, const float* __restrict__ alpha,
    float* __restrict__ out, int mode)
{
    __shared__ float As[16][132];   // transposed X tile: As[k][m]
    __shared__ float Bs[16][128];   // W tile: Bs[k][n]

    const int tid = threadIdx.x;
    const int tx = tid & 15;        // 0..15 (col group)
    const int ty = tid >> 4;        // 0..15 (row group)
    const int c0 = blockIdx.x * 128;
    const int r0 = blockIdx.y * 128;

    float acc[8][8];
    #pragma unroll
    for (int i = 0; i < 8; ++i)
        #pragma unroll
        for (int j = 0; j < 8; ++j) acc[i][j] = 0.0f;

    for (int kt = 0; kt < 1024; kt += 16) {
        // Load X tile (128 rows x 16 cols), store transposed
        #pragma unroll
        for (int t = 0; t < 2; ++t) {
            int idx  = tid + t * 256;        // 0..511 float4 slots
            int row  = idx >> 2;             // 0..127
            int col4 = (idx & 3) * 4;        // 0,4,8,12
            float4 v = *(const float4*)(X + (size_t)(r0 + row) * 1024 + kt + col4);
            As[col4 + 0][row] = v.x;
            As[col4 + 1][row] = v.y;
            As[col4 + 2][row] = v.z;
            As[col4 + 3][row] = v.w;
        }
        // Load W tile (16 rows x 128 cols)
        #pragma unroll
        for (int t = 0; t < 2; ++t) {
            int idx  = tid + t * 256;
            int row  = idx >> 5;             // 0..15
            int col4 = (idx & 31) * 4;       // 0..124
            *(float4*)&Bs[row][col4] =
                *(const float4*)(W + (size_t)(kt + row) * 1024 + c0 + col4);
        }
        __syncthreads();

        #pragma unroll
        for (int kk = 0; kk < 16; ++kk) {
            float ra[8], rb[8];
            #pragma unroll
            for (int i = 0; i < 8; ++i) ra[i] = As[kk][ty * 8 + i];
            float4 b0 = *(float4*)&Bs[kk][tx * 8];
            float4 b1 = *(float4*)&Bs[kk][tx * 8 + 4];
            rb[0] = b0.x; rb[1] = b0.y; rb[2] = b0.z; rb[3] = b0.w;
            rb[4] = b1.x; rb[5] = b1.y; rb[6] = b1.z; rb[7] = b1.w;
            #pragma unroll
            for (int i = 0; i < 8; ++i)
                #pragma unroll
                for (int j = 0; j < 8; ++j)
                    acc[i][j] += ra[i] * rb[j];
        }
        __syncthreads();
    }

    // Epilogue
    #pragma unroll
    for (int i = 0; i < 8; ++i) {
        int r = r0 + ty * 8 + i;
        float sc = (mode == 1) ? (1.0f + alpha[r]) : 1.0f;
        int b = r >> 11;
        int n = r & (N_ - 1);
        #pragma unroll
        for (int j = 0; j < 8; ++j) {
            int c = c0 + tx * 8 + j;
            float v = acc[i][j] + bvec[c];
            if (mode == 2) {
                out[(size_t)r * 1024 + c] = v;
            } else {
                int h  = c >> 6;
                int dk = c & 63;
                out[(((size_t)(b * H_ + h)) * N_ + n) * DK_ + dk] = v * sc;
            }
        }
    }
}

// ---------------------------------------------------------------------------
// Flash attention, fp32. One block = (head h, 64-query tile, batch b).
// Online softmax over 32 key tiles of 64. Bias read from gmem (L2-shared
// across heads: gridDim.x = H so consecutive blocks reuse bias rows).
// Smem: Qs[64][64], Ks[64][65] (reused as P tile), Vs[64][65].
// ---------------------------------------------------------------------------
__global__ __launch_bounds__(256) void attn_kernel(
    const float* __restrict__ bias, float* __restrict__ Y)
{
    extern __shared__ float sm[];
    float* Qs = sm;                      // 64*64
    float* Ks = sm + 64 * 64;            // 64*65  (aliased as P after S compute)
    float* Vs = Ks + 64 * 65;            // 64*65

    const int h   = blockIdx.x;
    const int qt  = blockIdx.y;
    const int b   = blockIdx.z;
    const int tid = threadIdx.x;
    const int tj  = tid & 15;            // key-col group (4 cols)
    const int ti  = tid >> 4;            // query-row group (4 rows)
    const int q0  = qt * 64;

    const float* Qg = g_Q + (((size_t)(b * H_ + h)) * N_ + q0) * DK_;
    const float* Kg = g_K + ((size_t)(b * H_ + h)) * N_ * DK_;
    const float* Vg = g_V + ((size_t)(b * H_ + h)) * N_ * DK_;
    const float* biasrow = bias + ((size_t)b * N_ + q0) * N_;

    // Load Q tile: 4096 floats, 16/thread
    #pragma unroll
    for (int t = 0; t < 4; ++t) {
        int idx = tid + t * 256;         // float4 index 0..1023
        int row = idx >> 4;              // 0..63
        int c4  = (idx & 15) * 4;
        *(float4*)(Qs + row * 64 + c4) = *(const float4*)(Qg + row * 64 + c4);
    }

    float m[4], l[4], acc[4][4];
    #pragma unroll
    for (int r = 0; r < 4; ++r) {
        m[r] = -1e30f; l[r] = 0.0f;
        #pragma unroll
        for (int c = 0; c < 4; ++c) acc[r][c] = 0.0f;
    }

    for (int k0 = 0; k0 < N_; k0 += 64) {
        __syncthreads();   // prev PV done (and Q load done on first iter)

        // Load K,V tiles (scalar stores into padded rows)
        #pragma unroll
        for (int t = 0; t < 4; ++t) {
            int idx = tid + t * 256;
            int row = idx >> 4;
            int c4  = (idx & 15) * 4;
            float4 kv = *(const float4*)(Kg + (size_t)(k0 + row) * 64 + c4);
            Ks[row * 65 + c4 + 0] = kv.x; Ks[row * 65 + c4 + 1] = kv.y;
            Ks[row * 65 + c4 + 2] = kv.z; Ks[row * 65 + c4 + 3] = kv.w;
            float4 vv = *(const float4*)(Vg + (size_t)(k0 + row) * 64 + c4);
            Vs[row * 65 + c4 + 0] = vv.x; Vs[row * 65 + c4 + 1] = vv.y;
            Vs[row * 65 + c4 + 2] = vv.z; Vs[row * 65 + c4 + 3] = vv.w;
        }
        __syncthreads();

        // S = (Q K^T) * 1/8 + bias   (4x4 per thread)
        float s[4][4];
        #pragma unroll
        for (int r = 0; r < 4; ++r)
            #pragma unroll
            for (int c = 0; c < 4; ++c) s[r][c] = 0.0f;

        #pragma unroll 4
        for (int d = 0; d < 64; ++d) {
            float qv[4], kv[4];
            #pragma unroll
            for (int r = 0; r < 4; ++r) qv[r] = Qs[(ti * 4 + r) * 64 + d];
            #pragma unroll
            for (int c = 0; c < 4; ++c) kv[c] = Ks[(tj * 4 + c) * 65 + d];
            #pragma unroll
            for (int r = 0; r < 4; ++r)
                #pragma unroll
                for (int c = 0; c < 4; ++c)
                    s[r][c] += qv[r] * kv[c];
        }
        #pragma unroll
        for (int r = 0; r < 4; ++r) {
            const float* brow = biasrow + (size_t)(ti * 4 + r) * N_ + k0 + tj * 4;
            #pragma unroll
            for (int c = 0; c < 4; ++c)
                s[r][c] = s[r][c] * 0.125f + brow[c];
        }

        // Online softmax update (row reductions over the 16 tj lanes)
        #pragma unroll
        for (int r = 0; r < 4; ++r) {
            float mt = fmaxf(fmaxf(s[r][0], s[r][1]), fmaxf(s[r][2], s[r][3]));
            #pragma unroll
            for (int o = 8; o >= 1; o >>= 1)
                mt = fmaxf(mt, __shfl_xor_sync(0xffffffffu, mt, o));
            float mn   = fmaxf(m[r], mt);
            float corr = __expf(m[r] - mn);
            m[r] = mn;
            float ls = 0.0f;
            #pragma unroll
            for (int c = 0; c < 4; ++c) {
                s[r][c] = __expf(s[r][c] - mn);
                ls += s[r][c];
            }
            #pragma unroll
            for (int o = 8; o >= 1; o >>= 1)
                ls += __shfl_xor_sync(0xffffffffu, ls, o);
            l[r] = l[r] * corr + ls;
            #pragma unroll
            for (int c = 0; c < 4; ++c) acc[r][c] *= corr;
        }

        __syncthreads();   // everyone done reading Ks -> safe to overwrite as P
        float* Ps = Ks;
        #pragma unroll
        for (int r = 0; r < 4; ++r)
            #pragma unroll
            for (int c = 0; c < 4; ++c)
                Ps[(ti * 4 + r) * 65 + tj * 4 + c] = s[r][c];
        __syncthreads();

        // O += P @ V
        #pragma unroll 4
        for (int j = 0; j < 64; ++j) {
            float pv[4], vv[4];
            #pragma unroll
            for (int r = 0; r < 4; ++r) pv[r] = Ps[(ti * 4 + r) * 65 + j];
            #pragma unroll
            for (int c = 0; c < 4; ++c) vv[c] = Vs[j * 65 + tj * 4 + c];
            #pragma unroll
            for (int r = 0; r < 4; ++r)
                #pragma unroll
                for (int c = 0; c < 4; ++c)
                    acc[r][c] += pv[r] * vv[c];
        }
    }

    // Write Y[b][n][h*64+dk]
    #pragma unroll
    for (int r = 0; r < 4; ++r) {
        float inv = 1.0f / l[r];
        int n = q0 + ti * 4 + r;
        float4 o;
        o.x = acc[r][0] * inv; o.y = acc[r][1] * inv;
        o.z = acc[r][2] * inv; o.w = acc[r][3] * inv;
        *(float4*)(Y + ((size_t)b * N_ + n) * D_ + h * 64 + tj * 4) = o;
    }
}

// ---------------------------------------------------------------------------
extern "C" void kernel_launch(void* const* d_in, const int* in_sizes, int n_in,
                              void* d_out, int out_size)
{
    const float* x     = (const float*)d_in[0];
    const float* alpha = (const float*)d_in[1];
    const float* bias  = (const float*)d_in[2];
    const float* Wq    = (const float*)d_in[3];
    const float* bq    = (const float*)d_in[4];
    const float* Wk    = (const float*)d_in[5];
    const float* bk    = (const float*)d_in[6];
    const float* Wv    = (const float*)d_in[7];
    const float* bv    = (const float*)d_in[8];
    const float* Wo    = (const float*)d_in[9];
    const float* bo    = (const float*)d_in[10];
    float* out = (float*)d_out;

    float *qp, *kp, *vp, *yp;
    cudaGetSymbolAddress((void**)&qp, g_Q);
    cudaGetSymbolAddress((void**)&kp, g_K);
    cudaGetSymbolAddress((void**)&vp, g_V);
    cudaGetSymbolAddress((void**)&yp, g_Y);

    const size_t attn_smem = (size_t)(64 * 64 + 64 * 65 + 64 * 65) * sizeof(float);
    cudaFuncSetAttribute(attn_kernel,
                         cudaFuncAttributeMaxDynamicSharedMemorySize,
                         (int)attn_smem);

    dim3 gg(8, 32), blk(256);
    sgemm_kernel<<<gg, blk>>>(x, Wq, bq, alpha, qp, 0);
    sgemm_kernel<<<gg, blk>>>(x, Wk, bk, alpha, kp, 1);
    sgemm_kernel<<<gg, blk>>>(x, Wv, bv, alpha, vp, 1);
    attn_kernel<<<dim3(H_, N_ / 64, B_), blk, attn_smem>>>(bias, yp);
    sgemm_kernel<<<gg, blk>>>(yp, Wo, bo, alpha, out, 2);
}

// round 3
// speedup vs baseline: 1.4494x; 1.4494x over previous
#include <cuda_runtime.h>
#include <cuda_bf16.h>
#include <cstdint>
#include <math.h>

#define B_   2
#define N_   2048
#define D_   1024
#define H_   16
#define DK_  64
#define M_   (B_ * N_)   // 4096

// ---------------- scratch (allocation-free rule: __device__ globals) -------
__device__ float g_Q[B_ * H_ * N_ * DK_];
__device__ float g_K[B_ * H_ * N_ * DK_];
__device__ float g_V[B_ * H_ * N_ * DK_];
__device__ float g_Y[M_ * D_];
__device__ __nv_bfloat16 g_Ah[M_ * D_];     // activation hi/lo (x, then y)
__device__ __nv_bfloat16 g_Al[M_ * D_];
__device__ __nv_bfloat16 g_Wh[4][D_ * D_];  // transposed weights [n][k], hi
__device__ __nv_bfloat16 g_Wl[4][D_ * D_];  // lo

// ---------------- PTX helpers (baseline ISA only: sm_80-level) -------------
__device__ __forceinline__ uint32_t smem_u32(const void* p) {
    uint32_t a;
    asm("{ .reg .u64 t; cvta.to.shared.u64 t, %1; cvt.u32.u64 %0, t; }"
        : "=r"(a) : "l"(p));
    return a;
}
__device__ __forceinline__ void ldmx4(uint32_t& r0, uint32_t& r1,
                                      uint32_t& r2, uint32_t& r3, uint32_t a) {
    asm volatile("ldmatrix.sync.aligned.m8n8.x4.shared.b16 {%0,%1,%2,%3}, [%4];"
                 : "=r"(r0), "=r"(r1), "=r"(r2), "=r"(r3) : "r"(a));
}
__device__ __forceinline__ void ldmx2(uint32_t& r0, uint32_t& r1, uint32_t a) {
    asm volatile("ldmatrix.sync.aligned.m8n8.x2.shared.b16 {%0,%1}, [%2];"
                 : "=r"(r0), "=r"(r1) : "r"(a));
}
__device__ __forceinline__ void mma16816(float* c, const uint32_t* a,
                                         const uint32_t* b) {
    asm volatile(
        "mma.sync.aligned.m16n8k16.row.col.f32.bf16.bf16.f32 "
        "{%0,%1,%2,%3}, {%4,%5,%6,%7}, {%8,%9}, {%0,%1,%2,%3};"
        : "+f"(c[0]), "+f"(c[1]), "+f"(c[2]), "+f"(c[3])
        : "r"(a[0]), "r"(a[1]), "r"(a[2]), "r"(a[3]), "r"(b[0]), "r"(b[1]));
}

// ---------------------------------------------------------------------------
// split: fp32 -> bf16 hi + bf16 lo (elementwise), 4M elements
// ---------------------------------------------------------------------------
__global__ __launch_bounds__(256) void split_kernel(
    const float* __restrict__ X, __nv_bfloat16* __restrict__ Hh,
    __nv_bfloat16* __restrict__ Hl)
{
    int i = blockIdx.x * 256 + threadIdx.x;   // float4 index, 1M total
    float4 v = *(const float4*)(X + (size_t)i * 4);
    __nv_bfloat16 h0 = __float2bfloat16(v.x), h1 = __float2bfloat16(v.y);
    __nv_bfloat16 h2 = __float2bfloat16(v.z), h3 = __float2bfloat16(v.w);
    __nv_bfloat16 l0 = __float2bfloat16(v.x - __bfloat162float(h0));
    __nv_bfloat16 l1 = __float2bfloat16(v.y - __bfloat162float(h1));
    __nv_bfloat16 l2 = __float2bfloat16(v.z - __bfloat162float(h2));
    __nv_bfloat16 l3 = __float2bfloat16(v.w - __bfloat162float(h3));
    __nv_bfloat162* ph = (__nv_bfloat162*)(Hh + (size_t)i * 4);
    __nv_bfloat162* pl = (__nv_bfloat162*)(Hl + (size_t)i * 4);
    ph[0] = __nv_bfloat162(h0, h1); ph[1] = __nv_bfloat162(h2, h3);
    pl[0] = __nv_bfloat162(l0, l1); pl[1] = __nv_bfloat162(l2, l3);
}

// ---------------------------------------------------------------------------
// wsplit: W[k][n] fp32 -> Th[n][k], Tl[n][k] bf16 (transpose + split)
// ---------------------------------------------------------------------------
__global__ __launch_bounds__(256) void wsplit_kernel(
    const float* __restrict__ W, __nv_bfloat16* __restrict__ Th,
    __nv_bfloat16* __restrict__ Tl)
{
    __shared__ float t[32][33];
    int k0 = blockIdx.x * 32, n0 = blockIdx.y * 32;
    int tx = threadIdx.x & 31, ty = threadIdx.x >> 5;
    #pragma unroll
    for (int j = ty; j < 32; j += 8)
        t[j][tx] = W[(size_t)(k0 + j) * D_ + n0 + tx];
    __syncthreads();
    #pragma unroll
    for (int j = ty; j < 32; j += 8) {
        float v = t[tx][j];   // = W[k0+tx][n0+j]
        __nv_bfloat16 h = __float2bfloat16(v);
        size_t o = (size_t)(n0 + j) * D_ + k0 + tx;
        Th[o] = h;
        Tl[o] = __float2bfloat16(v - __bfloat162float(h));
    }
}

// ---------------------------------------------------------------------------
// mma.sync GEMM: C[4096,1024] = (Ah+Al)[M,K] @ (Bh+Bl)[N,K]^T + bvec
// 3-term bf16 split, fp32 register accumulators.
// CTA tile 128x128, k-tile 32, double-buffered smem. 8 warps in 2x4 grid,
// warp tile 64x32, mma m16n8k16.
// mode 0: head-major out (Q); 1: head-major*(1+alpha) (K/V); 2: row-major.
// ---------------------------------------------------------------------------
#define KSTRIDE 80          // bytes per smem row (32 bf16 + 8 pad)
#define TILE_B  10240       // one 128x32 bf16 tile in smem
#define STAGE_B (4 * TILE_B)

__global__ __launch_bounds__(256) void gemm_mma(
    const __nv_bfloat16* __restrict__ Ah, const __nv_bfloat16* __restrict__ Al,
    const __nv_bfloat16* __restrict__ Bh, const __nv_bfloat16* __restrict__ Bl,
    const float* __restrict__ bvec, const float* __restrict__ alpha,
    float* __restrict__ out, int mode)
{
    extern __shared__ char smraw[];
    const uint32_t smb = smem_u32(smraw);

    const int tid  = threadIdx.x;
    const int lane = tid & 31;
    const int wid  = tid >> 5;
    const int wm   = wid >> 2;          // 0..1
    const int wn   = wid & 3;           // 0..3
    const int c0   = blockIdx.x * 128;
    const int r0   = blockIdx.y * 128;

    // gmem base pointers for this CTA's tiles
    const __nv_bfloat16* gAh = Ah + (size_t)r0 * D_;
    const __nv_bfloat16* gAl = Al + (size_t)r0 * D_;
    const __nv_bfloat16* gBh = Bh + (size_t)c0 * D_;
    const __nv_bfloat16* gBl = Bl + (size_t)c0 * D_;

    // per-thread load slots: idx = tid + t*256, t in 0..1 (512 float4/tile)
    // row = idx>>2 (0..127), col8 = (idx&3)*8 bf16
    int li0 = tid, li1 = tid + 256;
    int lr0 = li0 >> 2, lc0 = (li0 & 3) * 8;
    int lr1 = li1 >> 2, lc1 = (li1 & 3) * 8;
    size_t go0 = (size_t)lr0 * D_ + lc0;
    size_t go1 = (size_t)lr1 * D_ + lc1;
    uint32_t so0 = (uint32_t)(lr0 * KSTRIDE + lc0 * 2);
    uint32_t so1 = (uint32_t)(lr1 * KSTRIDE + lc1 * 2);

    // ldmatrix per-lane row offsets (byte offsets within a tile)
    uint32_t a_off[4], b_off[4];
    #pragma unroll
    for (int i = 0; i < 4; ++i)
        a_off[i] = (uint32_t)((wm * 64 + i * 16 + (lane & 15)) * KSTRIDE
                              + (lane >> 4) * 16);
    #pragma unroll
    for (int j = 0; j < 4; ++j)
        b_off[j] = (uint32_t)((wn * 32 + j * 8 + (lane & 7)) * KSTRIDE
                              + ((lane >> 3) & 1) * 16);

    float acc[4][4][4];
    #pragma unroll
    for (int i = 0; i < 4; ++i)
        #pragma unroll
        for (int j = 0; j < 4; ++j)
            #pragma unroll
            for (int e = 0; e < 4; ++e) acc[i][j][e] = 0.0f;

    // ---- prologue: fill stage 0 directly ----
    {
        uint32_t s = smb;
        *(float4*)(smraw + (s - smb) + 0) = *(float4*)(smraw);  // no-op guard
        float4 v;
        v = *(const float4*)(gAh + go0); *(float4*)((char*)smraw + 0*TILE_B + so0) = v;
        v = *(const float4*)(gAh + go1); *(float4*)((char*)smraw + 0*TILE_B + so1) = v;
        v = *(const float4*)(gAl + go0); *(float4*)((char*)smraw + 1*TILE_B + so0) = v;
        v = *(const float4*)(gAl + go1); *(float4*)((char*)smraw + 1*TILE_B + so1) = v;
        v = *(const float4*)(gBh + go0); *(float4*)((char*)smraw + 2*TILE_B + so0) = v;
        v = *(const float4*)(gBh + go1); *(float4*)((char*)smraw + 2*TILE_B + so1) = v;
        v = *(const float4*)(gBl + go0); *(float4*)((char*)smraw + 3*TILE_B + so0) = v;
        v = *(const float4*)(gBl + go1); *(float4*)((char*)smraw + 3*TILE_B + so1) = v;
    }
    __syncthreads();

    for (int kc = 0; kc < 32; ++kc) {
        // prefetch next k-tile into registers
        float4 nAh0, nAh1, nAl0, nAl1, nBh0, nBh1, nBl0, nBl1;
        if (kc + 1 < 32) {
            size_t ko = (size_t)(kc + 1) * 32;
            nAh0 = *(const float4*)(gAh + go0 + ko);
            nAh1 = *(const float4*)(gAh + go1 + ko);
            nAl0 = *(const float4*)(gAl + go0 + ko);
            nAl1 = *(const float4*)(gAl + go1 + ko);
            nBh0 = *(const float4*)(gBh + go0 + ko);
            nBh1 = *(const float4*)(gBh + go1 + ko);
            nBl0 = *(const float4*)(gBl + go0 + ko);
            nBl1 = *(const float4*)(gBl + go1 + ko);
        }

        // compute on current stage
        uint32_t st = smb + (uint32_t)(kc & 1) * STAGE_B;
        uint32_t sAh = st, sAl = st + TILE_B, sBh = st + 2 * TILE_B,
                 sBl = st + 3 * TILE_B;
        #pragma unroll
        for (int ks = 0; ks < 2; ++ks) {
            uint32_t kb = (uint32_t)(ks * 32);   // k16 step -> 32 bytes
            uint32_t ah[4][4], al[4][4], bh[4][2], bl[4][2];
            #pragma unroll
            for (int j = 0; j < 4; ++j) {
                ldmx2(bh[j][0], bh[j][1], sBh + b_off[j] + kb);
                ldmx2(bl[j][0], bl[j][1], sBl + b_off[j] + kb);
            }
            #pragma unroll
            for (int i = 0; i < 4; ++i) {
                ldmx4(ah[i][0], ah[i][1], ah[i][2], ah[i][3], sAh + a_off[i] + kb);
                ldmx4(al[i][0], al[i][1], al[i][2], al[i][3], sAl + a_off[i] + kb);
            }
            #pragma unroll
            for (int i = 0; i < 4; ++i)
                #pragma unroll
                for (int j = 0; j < 4; ++j) {
                    mma16816(acc[i][j], ah[i], bh[j]);
                    mma16816(acc[i][j], ah[i], bl[j]);
                    mma16816(acc[i][j], al[i], bh[j]);
                }
        }

        // store prefetched tile into the other stage
        if (kc + 1 < 32) {
            char* nst = (char*)smraw + (size_t)((kc + 1) & 1) * STAGE_B;
            *(float4*)(nst + 0*TILE_B + so0) = nAh0;
            *(float4*)(nst + 0*TILE_B + so1) = nAh1;
            *(float4*)(nst + 1*TILE_B + so0) = nAl0;
            *(float4*)(nst + 1*TILE_B + so1) = nAl1;
            *(float4*)(nst + 2*TILE_B + so0) = nBh0;
            *(float4*)(nst + 2*TILE_B + so1) = nBh1;
            *(float4*)(nst + 3*TILE_B + so0) = nBl0;
            *(float4*)(nst + 3*TILE_B + so1) = nBl1;
        }
        __syncthreads();
    }

    // ---- epilogue: bias + optional alpha scale + scatter ----
    #pragma unroll
    for (int i = 0; i < 4; ++i) {
        #pragma unroll
        for (int part = 0; part < 2; ++part) {
            int r = r0 + wm * 64 + i * 16 + (lane >> 2) + part * 8;
            float sc = (mode == 1) ? (1.0f + alpha[r]) : 1.0f;
            int b = r >> 11, n = r & (N_ - 1);
            #pragma unroll
            for (int j = 0; j < 4; ++j) {
                int c = c0 + wn * 32 + j * 8 + (lane & 3) * 2;
                float2 o;
                o.x = (acc[i][j][part * 2 + 0] + bvec[c + 0]) * sc;
                o.y = (acc[i][j][part * 2 + 1] + bvec[c + 1]) * sc;
                if (mode == 2) {
                    *(float2*)(out + (size_t)r * D_ + c) = o;
                } else {
                    int h = c >> 6, dk = c & 63;
                    *(float2*)(out + (((size_t)(b * H_ + h)) * N_ + n) * DK_ + dk) = o;
                }
            }
        }
    }
}

// ---------------------------------------------------------------------------
// Flash attention, fp32 (unchanged from R1 — passes).
// ---------------------------------------------------------------------------
__global__ __launch_bounds__(256) void attn_kernel(
    const float* __restrict__ bias, float* __restrict__ Y)
{
    extern __shared__ float sm[];
    float* Qs = sm;
    float* Ks = sm + 64 * 64;
    float* Vs = Ks + 64 * 65;

    const int h   = blockIdx.x;
    const int qt  = blockIdx.y;
    const int b   = blockIdx.z;
    const int tid = threadIdx.x;
    const int tj  = tid & 15;
    const int ti  = tid >> 4;
    const int q0  = qt * 64;

    const float* Qg = g_Q + (((size_t)(b * H_ + h)) * N_ + q0) * DK_;
    const float* Kg = g_K + ((size_t)(b * H_ + h)) * N_ * DK_;
    const float* Vg = g_V + ((size_t)(b * H_ + h)) * N_ * DK_;
    const float* biasrow = bias + ((size_t)b * N_ + q0) * N_;

    #pragma unroll
    for (int t = 0; t < 4; ++t) {
        int idx = tid + t * 256;
        int row = idx >> 4;
        int c4  = (idx & 15) * 4;
        *(float4*)(Qs + row * 64 + c4) = *(const float4*)(Qg + row * 64 + c4);
    }

    float m[4], l[4], acc[4][4];
    #pragma unroll
    for (int r = 0; r < 4; ++r) {
        m[r] = -1e30f; l[r] = 0.0f;
        #pragma unroll
        for (int c = 0; c < 4; ++c) acc[r][c] = 0.0f;
    }

    for (int k0 = 0; k0 < N_; k0 += 64) {
        __syncthreads();
        #pragma unroll
        for (int t = 0; t < 4; ++t) {
            int idx = tid + t * 256;
            int row = idx >> 4;
            int c4  = (idx & 15) * 4;
            float4 kv = *(const float4*)(Kg + (size_t)(k0 + row) * 64 + c4);
            Ks[row * 65 + c4 + 0] = kv.x; Ks[row * 65 + c4 + 1] = kv.y;
            Ks[row * 65 + c4 + 2] = kv.z; Ks[row * 65 + c4 + 3] = kv.w;
            float4 vv = *(const float4*)(Vg + (size_t)(k0 + row) * 64 + c4);
            Vs[row * 65 + c4 + 0] = vv.x; Vs[row * 65 + c4 + 1] = vv.y;
            Vs[row * 65 + c4 + 2] = vv.z; Vs[row * 65 + c4 + 3] = vv.w;
        }
        __syncthreads();

        float s[4][4];
        #pragma unroll
        for (int r = 0; r < 4; ++r)
            #pragma unroll
            for (int c = 0; c < 4; ++c) s[r][c] = 0.0f;

        #pragma unroll 4
        for (int d = 0; d < 64; ++d) {
            float qv[4], kv[4];
            #pragma unroll
            for (int r = 0; r < 4; ++r) qv[r] = Qs[(ti * 4 + r) * 64 + d];
            #pragma unroll
            for (int c = 0; c < 4; ++c) kv[c] = Ks[(tj * 4 + c) * 65 + d];
            #pragma unroll
            for (int r = 0; r < 4; ++r)
                #pragma unroll
                for (int c = 0; c < 4; ++c)
                    s[r][c] += qv[r] * kv[c];
        }
        #pragma unroll
        for (int r = 0; r < 4; ++r) {
            const float* brow = biasrow + (size_t)(ti * 4 + r) * N_ + k0 + tj * 4;
            #pragma unroll
            for (int c = 0; c < 4; ++c)
                s[r][c] = s[r][c] * 0.125f + brow[c];
        }

        #pragma unroll
        for (int r = 0; r < 4; ++r) {
            float mt = fmaxf(fmaxf(s[r][0], s[r][1]), fmaxf(s[r][2], s[r][3]));
            #pragma unroll
            for (int o = 8; o >= 1; o >>= 1)
                mt = fmaxf(mt, __shfl_xor_sync(0xffffffffu, mt, o));
            float mn   = fmaxf(m[r], mt);
            float corr = __expf(m[r] - mn);
            m[r] = mn;
            float ls = 0.0f;
            #pragma unroll
            for (int c = 0; c < 4; ++c) {
                s[r][c] = __expf(s[r][c] - mn);
                ls += s[r][c];
            }
            #pragma unroll
            for (int o = 8; o >= 1; o >>= 1)
                ls += __shfl_xor_sync(0xffffffffu, ls, o);
            l[r] = l[r] * corr + ls;
            #pragma unroll
            for (int c = 0; c < 4; ++c) acc[r][c] *= corr;
        }

        __syncthreads();
        float* Ps = Ks;
        #pragma unroll
        for (int r = 0; r < 4; ++r)
            #pragma unroll
            for (int c = 0; c < 4; ++c)
                Ps[(ti * 4 + r) * 65 + tj * 4 + c] = s[r][c];
        __syncthreads();

        #pragma unroll 4
        for (int j = 0; j < 64; ++j) {
            float pv[4], vv[4];
            #pragma unroll
            for (int r = 0; r < 4; ++r) pv[r] = Ps[(ti * 4 + r) * 65 + j];
            #pragma unroll
            for (int c = 0; c < 4; ++c) vv[c] = Vs[j * 65 + tj * 4 + c];
            #pragma unroll
            for (int r = 0; r < 4; ++r)
                #pragma unroll
                for (int c = 0; c < 4; ++c)
                    acc[r][c] += pv[r] * vv[c];
        }
    }

    #pragma unroll
    for (int r = 0; r < 4; ++r) {
        float inv = 1.0f / l[r];
        int n = q0 + ti * 4 + r;
        float4 o;
        o.x = acc[r][0] * inv; o.y = acc[r][1] * inv;
        o.z = acc[r][2] * inv; o.w = acc[r][3] * inv;
        *(float4*)(Y + ((size_t)b * N_ + n) * D_ + h * 64 + tj * 4) = o;
    }
}

// ---------------------------------------------------------------------------
extern "C" void kernel_launch(void* const* d_in, const int* in_sizes, int n_in,
                              void* d_out, int out_size)
{
    const float* x     = (const float*)d_in[0];
    const float* alpha = (const float*)d_in[1];
    const float* bias  = (const float*)d_in[2];
    const float* Wq    = (const float*)d_in[3];
    const float* bq    = (const float*)d_in[4];
    const float* Wk    = (const float*)d_in[5];
    const float* bk    = (const float*)d_in[6];
    const float* Wv    = (const float*)d_in[7];
    const float* bv    = (const float*)d_in[8];
    const float* Wo    = (const float*)d_in[9];
    const float* bo    = (const float*)d_in[10];
    float* out = (float*)d_out;

    float *qp, *kp, *vp, *yp;
    __nv_bfloat16 *ahp, *alp, *whp, *wlp;
    cudaGetSymbolAddress((void**)&qp, g_Q);
    cudaGetSymbolAddress((void**)&kp, g_K);
    cudaGetSymbolAddress((void**)&vp, g_V);
    cudaGetSymbolAddress((void**)&yp, g_Y);
    cudaGetSymbolAddress((void**)&ahp, g_Ah);
    cudaGetSymbolAddress((void**)&alp, g_Al);
    cudaGetSymbolAddress((void**)&whp, g_Wh);
    cudaGetSymbolAddress((void**)&wlp, g_Wl);

    const int gemm_smem = 2 * STAGE_B;   // 81920
    cudaFuncSetAttribute(gemm_mma, cudaFuncAttributeMaxDynamicSharedMemorySize,
                         gemm_smem);
    const size_t attn_smem = (size_t)(64 * 64 + 64 * 65 + 64 * 65) * sizeof(float);
    cudaFuncSetAttribute(attn_kernel, cudaFuncAttributeMaxDynamicSharedMemorySize,
                         (int)attn_smem);

    dim3 blk(256);
    dim3 gw(32, 32);
    split_kernel<<<4096, blk>>>(x, ahp, alp);
    wsplit_kernel<<<gw, blk>>>(Wq, whp + 0 * (size_t)D_ * D_, wlp + 0 * (size_t)D_ * D_);
    wsplit_kernel<<<gw, blk>>>(Wk, whp + 1 * (size_t)D_ * D_, wlp + 1 * (size_t)D_ * D_);
    wsplit_kernel<<<gw, blk>>>(Wv, whp + 2 * (size_t)D_ * D_, wlp + 2 * (size_t)D_ * D_);
    wsplit_kernel<<<gw, blk>>>(Wo, whp + 3 * (size_t)D_ * D_, wlp + 3 * (size_t)D_ * D_);

    dim3 gg(8, 32);
    gemm_mma<<<gg, blk, gemm_smem>>>(ahp, alp,
        whp + 0 * (size_t)D_ * D_, wlp + 0 * (size_t)D_ * D_, bq, alpha, qp, 0);
    gemm_mma<<<gg, blk, gemm_smem>>>(ahp, alp,
        whp + 1 * (size_t)D_ * D_, wlp + 1 * (size_t)D_ * D_, bk, alpha, kp, 1);
    gemm_mma<<<gg, blk, gemm_smem>>>(ahp, alp,
        whp + 2 * (size_t)D_ * D_, wlp + 2 * (size_t)D_ * D_, bv, alpha, vp, 1);

    attn_kernel<<<dim3(H_, N_ / 64, B_), blk, attn_smem>>>(bias, yp);

    split_kernel<<<4096, blk>>>(yp, ahp, alp);
    gemm_mma<<<gg, blk, gemm_smem>>>(ahp, alp,
        whp + 3 * (size_t)D_ * D_, wlp + 3 * (size_t)D_ * D_, bo, alpha, out, 2);
}

// round 4
// speedup vs baseline: 2.6529x; 1.8303x over previous
#include <cuda_runtime.h>
#include <cuda_bf16.h>
#include <cstdint>
#include <math.h>

#define B_   2
#define N_   2048
#define D_   1024
#define H_   16
#define DK_  64
#define M_   (B_ * N_)   // 4096

// ---------------- scratch (allocation-free rule: __device__ globals) -------
__device__ __nv_bfloat16 g_Ah[M_ * D_];     // x split, later Y split
__device__ __nv_bfloat16 g_Al[M_ * D_];
__device__ __nv_bfloat16 g_Wh[4][D_ * D_];  // transposed weights [n][k], hi
__device__ __nv_bfloat16 g_Wl[4][D_ * D_];  // lo
__device__ __nv_bfloat16 g_Qh[B_ * H_ * N_ * DK_];
__device__ __nv_bfloat16 g_Ql[B_ * H_ * N_ * DK_];
__device__ __nv_bfloat16 g_Kh[B_ * H_ * N_ * DK_];
__device__ __nv_bfloat16 g_Kl[B_ * H_ * N_ * DK_];
__device__ __nv_bfloat16 g_Vh[B_ * H_ * N_ * DK_];
__device__ __nv_bfloat16 g_Vl[B_ * H_ * N_ * DK_];

// ---------------- PTX helpers (baseline ISA: sm_80-level only) -------------
__device__ __forceinline__ uint32_t smem_u32(const void* p) {
    uint32_t a;
    asm("{ .reg .u64 t; cvta.to.shared.u64 t, %1; cvt.u32.u64 %0, t; }"
        : "=r"(a) : "l"(p));
    return a;
}
__device__ __forceinline__ void ldmx4(uint32_t& r0, uint32_t& r1,
                                      uint32_t& r2, uint32_t& r3, uint32_t a) {
    asm volatile("ldmatrix.sync.aligned.m8n8.x4.shared.b16 {%0,%1,%2,%3}, [%4];"
                 : "=r"(r0), "=r"(r1), "=r"(r2), "=r"(r3) : "r"(a));
}
__device__ __forceinline__ void ldmx4t(uint32_t& r0, uint32_t& r1,
                                       uint32_t& r2, uint32_t& r3, uint32_t a) {
    asm volatile("ldmatrix.sync.aligned.m8n8.x4.trans.shared.b16 {%0,%1,%2,%3}, [%4];"
                 : "=r"(r0), "=r"(r1), "=r"(r2), "=r"(r3) : "r"(a));
}
__device__ __forceinline__ void ldmx2(uint32_t& r0, uint32_t& r1, uint32_t a) {
    asm volatile("ldmatrix.sync.aligned.m8n8.x2.shared.b16 {%0,%1}, [%2];"
                 : "=r"(r0), "=r"(r1) : "r"(a));
}
__device__ __forceinline__ void mma16816(float* c, const uint32_t* a,
                                         const uint32_t* b) {
    asm volatile(
        "mma.sync.aligned.m16n8k16.row.col.f32.bf16.bf16.f32 "
        "{%0,%1,%2,%3}, {%4,%5,%6,%7}, {%8,%9}, {%0,%1,%2,%3};"
        : "+f"(c[0]), "+f"(c[1]), "+f"(c[2]), "+f"(c[3])
        : "r"(a[0]), "r"(a[1]), "r"(a[2]), "r"(a[3]), "r"(b[0]), "r"(b[1]));
}
__device__ __forceinline__ void split2(float x, float y, uint32_t& h, uint32_t& l) {
    __nv_bfloat16 hx = __float2bfloat16(x), hy = __float2bfloat16(y);
    __nv_bfloat16 lx = __float2bfloat16(x - __bfloat162float(hx));
    __nv_bfloat16 ly = __float2bfloat16(y - __bfloat162float(hy));
    __nv_bfloat162 hp(hx, hy), lp(lx, ly);
    h = *(uint32_t*)&hp; l = *(uint32_t*)&lp;
}
#define CP16(dst, src) \
    asm volatile("cp.async.ca.shared.global [%0], [%1], 16;" :: "r"(dst), "l"(src))
#define CPCOMMIT() asm volatile("cp.async.commit_group;" ::: "memory")
#define CPWAIT(n)  asm volatile("cp.async.wait_group %0;" :: "n"(n) : "memory")

// ---------------------------------------------------------------------------
// split: fp32 -> bf16 hi + bf16 lo (elementwise)
// ---------------------------------------------------------------------------
__global__ __launch_bounds__(256) void split_kernel(
    const float* __restrict__ X, __nv_bfloat16* __restrict__ Hh,
    __nv_bfloat16* __restrict__ Hl)
{
    int i = blockIdx.x * 256 + threadIdx.x;
    float4 v = *(const float4*)(X + (size_t)i * 4);
    uint32_t h0, l0, h1, l1;
    split2(v.x, v.y, h0, l0);
    split2(v.z, v.w, h1, l1);
    uint32_t* ph = (uint32_t*)(Hh + (size_t)i * 4);
    uint32_t* pl = (uint32_t*)(Hl + (size_t)i * 4);
    ph[0] = h0; ph[1] = h1; pl[0] = l0; pl[1] = l1;
}

// ---------------------------------------------------------------------------
// wsplit: W[k][n] fp32 -> Th[n][k], Tl[n][k] bf16 (transpose + split)
// ---------------------------------------------------------------------------
__global__ __launch_bounds__(256) void wsplit_kernel(
    const float* __restrict__ W, __nv_bfloat16* __restrict__ Th,
    __nv_bfloat16* __restrict__ Tl)
{
    __shared__ float t[32][33];
    int k0 = blockIdx.x * 32, n0 = blockIdx.y * 32;
    int tx = threadIdx.x & 31, ty = threadIdx.x >> 5;
    #pragma unroll
    for (int j = ty; j < 32; j += 8)
        t[j][tx] = W[(size_t)(k0 + j) * D_ + n0 + tx];
    __syncthreads();
    #pragma unroll
    for (int j = ty; j < 32; j += 8) {
        float v = t[tx][j];
        __nv_bfloat16 h = __float2bfloat16(v);
        size_t o = (size_t)(n0 + j) * D_ + k0 + tx;
        Th[o] = h;
        Tl[o] = __float2bfloat16(v - __bfloat162float(h));
    }
}

// ---------------------------------------------------------------------------
// mma.sync GEMM (as R3), epilogue now writes bf16 hi/lo split for modes 0/1.
// mode 0: head-major split out (Q); 1: same * (1+alpha) (K/V); 2: fp32 row-major.
// ---------------------------------------------------------------------------
#define KSTRIDE 80
#define TILE_B  10240
#define STAGE_B (4 * TILE_B)

__global__ __launch_bounds__(256) void gemm_mma(
    const __nv_bfloat16* __restrict__ Ah, const __nv_bfloat16* __restrict__ Al,
    const __nv_bfloat16* __restrict__ Bh, const __nv_bfloat16* __restrict__ Bl,
    const float* __restrict__ bvec, const float* __restrict__ alpha,
    float* __restrict__ outf, __nv_bfloat16* __restrict__ outh,
    __nv_bfloat16* __restrict__ outl, int mode)
{
    extern __shared__ char smraw[];

    const int tid  = threadIdx.x;
    const int lane = tid & 31;
    const int wid  = tid >> 5;
    const int wm   = wid >> 2;
    const int wn   = wid & 3;
    const int c0   = blockIdx.x * 128;
    const int r0   = blockIdx.y * 128;
    const uint32_t smb = smem_u32(smraw);

    const __nv_bfloat16* gAh = Ah + (size_t)r0 * D_;
    const __nv_bfloat16* gAl = Al + (size_t)r0 * D_;
    const __nv_bfloat16* gBh = Bh + (size_t)c0 * D_;
    const __nv_bfloat16* gBl = Bl + (size_t)c0 * D_;

    int li0 = tid, li1 = tid + 256;
    int lr0 = li0 >> 2, lc0 = (li0 & 3) * 8;
    int lr1 = li1 >> 2, lc1 = (li1 & 3) * 8;
    size_t go0 = (size_t)lr0 * D_ + lc0;
    size_t go1 = (size_t)lr1 * D_ + lc1;
    uint32_t so0 = (uint32_t)(lr0 * KSTRIDE + lc0 * 2);
    uint32_t so1 = (uint32_t)(lr1 * KSTRIDE + lc1 * 2);

    uint32_t a_off[4], b_off[4];
    #pragma unroll
    for (int i = 0; i < 4; ++i)
        a_off[i] = (uint32_t)((wm * 64 + i * 16 + (lane & 15)) * KSTRIDE
                              + (lane >> 4) * 16);
    #pragma unroll
    for (int j = 0; j < 4; ++j)
        b_off[j] = (uint32_t)((wn * 32 + j * 8 + (lane & 7)) * KSTRIDE
                              + ((lane >> 3) & 1) * 16);

    float acc[4][4][4];
    #pragma unroll
    for (int i = 0; i < 4; ++i)
        #pragma unroll
        for (int j = 0; j < 4; ++j)
            #pragma unroll
            for (int e = 0; e < 4; ++e) acc[i][j][e] = 0.0f;

    {
        float4 v;
        v = *(const float4*)(gAh + go0); *(float4*)(smraw + 0*TILE_B + so0) = v;
        v = *(const float4*)(gAh + go1); *(float4*)(smraw + 0*TILE_B + so1) = v;
        v = *(const float4*)(gAl + go0); *(float4*)(smraw + 1*TILE_B + so0) = v;
        v = *(const float4*)(gAl + go1); *(float4*)(smraw + 1*TILE_B + so1) = v;
        v = *(const float4*)(gBh + go0); *(float4*)(smraw + 2*TILE_B + so0) = v;
        v = *(const float4*)(gBh + go1); *(float4*)(smraw + 2*TILE_B + so1) = v;
        v = *(const float4*)(gBl + go0); *(float4*)(smraw + 3*TILE_B + so0) = v;
        v = *(const float4*)(gBl + go1); *(float4*)(smraw + 3*TILE_B + so1) = v;
    }
    __syncthreads();

    for (int kc = 0; kc < 32; ++kc) {
        float4 nAh0, nAh1, nAl0, nAl1, nBh0, nBh1, nBl0, nBl1;
        if (kc + 1 < 32) {
            size_t ko = (size_t)(kc + 1) * 32;
            nAh0 = *(const float4*)(gAh + go0 + ko);
            nAh1 = *(const float4*)(gAh + go1 + ko);
            nAl0 = *(const float4*)(gAl + go0 + ko);
            nAl1 = *(const float4*)(gAl + go1 + ko);
            nBh0 = *(const float4*)(gBh + go0 + ko);
            nBh1 = *(const float4*)(gBh + go1 + ko);
            nBl0 = *(const float4*)(gBl + go0 + ko);
            nBl1 = *(const float4*)(gBl + go1 + ko);
        }

        uint32_t st = smb + (uint32_t)(kc & 1) * STAGE_B;
        uint32_t sAh = st, sAl = st + TILE_B, sBh = st + 2 * TILE_B,
                 sBl = st + 3 * TILE_B;
        #pragma unroll
        for (int ks = 0; ks < 2; ++ks) {
            uint32_t kb = (uint32_t)(ks * 32);
            uint32_t ah[4][4], al[4][4], bh[4][2], bl[4][2];
            #pragma unroll
            for (int j = 0; j < 4; ++j) {
                ldmx2(bh[j][0], bh[j][1], sBh + b_off[j] + kb);
                ldmx2(bl[j][0], bl[j][1], sBl + b_off[j] + kb);
            }
            #pragma unroll
            for (int i = 0; i < 4; ++i) {
                ldmx4(ah[i][0], ah[i][1], ah[i][2], ah[i][3], sAh + a_off[i] + kb);
                ldmx4(al[i][0], al[i][1], al[i][2], al[i][3], sAl + a_off[i] + kb);
            }
            #pragma unroll
            for (int i = 0; i < 4; ++i)
                #pragma unroll
                for (int j = 0; j < 4; ++j) {
                    mma16816(acc[i][j], ah[i], bh[j]);
                    mma16816(acc[i][j], ah[i], bl[j]);
                    mma16816(acc[i][j], al[i], bh[j]);
                }
        }

        if (kc + 1 < 32) {
            char* nst = (char*)smraw + (size_t)((kc + 1) & 1) * STAGE_B;
            *(float4*)(nst + 0*TILE_B + so0) = nAh0;
            *(float4*)(nst + 0*TILE_B + so1) = nAh1;
            *(float4*)(nst + 1*TILE_B + so0) = nAl0;
            *(float4*)(nst + 1*TILE_B + so1) = nAl1;
            *(float4*)(nst + 2*TILE_B + so0) = nBh0;
            *(float4*)(nst + 2*TILE_B + so1) = nBh1;
            *(float4*)(nst + 3*TILE_B + so0) = nBl0;
            *(float4*)(nst + 3*TILE_B + so1) = nBl1;
        }
        __syncthreads();
    }

    #pragma unroll
    for (int i = 0; i < 4; ++i) {
        #pragma unroll
        for (int part = 0; part < 2; ++part) {
            int r = r0 + wm * 64 + i * 16 + (lane >> 2) + part * 8;
            float sc = (mode == 1) ? (1.0f + alpha[r]) : 1.0f;
            int b = r >> 11, n = r & (N_ - 1);
            #pragma unroll
            for (int j = 0; j < 4; ++j) {
                int c = c0 + wn * 32 + j * 8 + (lane & 3) * 2;
                float v0 = (acc[i][j][part * 2 + 0] + bvec[c + 0]) * sc;
                float v1 = (acc[i][j][part * 2 + 1] + bvec[c + 1]) * sc;
                if (mode == 2) {
                    float2 o; o.x = v0; o.y = v1;
                    *(float2*)(outf + (size_t)r * D_ + c) = o;
                } else {
                    int hh = c >> 6, dk = c & 63;
                    size_t off = (((size_t)(b * H_ + hh)) * N_ + n) * DK_ + dk;
                    uint32_t uh, ul;
                    split2(v0, v1, uh, ul);
                    *(uint32_t*)(outh + off) = uh;
                    *(uint32_t*)(outl + off) = ul;
                }
            }
        }
    }
}

// ---------------------------------------------------------------------------
// Flash attention via mma.sync bf16 3-term split.
// CTA = (head, 128-q tile, batch); 8 warps (m16 each) x 64-key tiles.
// K/V hi/lo double-buffered via cp.async; P kept in registers (FA-2 trick).
// Output written as bf16 hi/lo split directly into g_Ah/g_Al.
// ---------------------------------------------------------------------------
#define QT    128
#define VSTR  144                // bytes per smem row (64 bf16 + 8 pad)
#define ATILE (64 * VSTR)        // 9216 bytes per 64x64 bf16 tile

__global__ __launch_bounds__(256) void attn_mma(
    const __nv_bfloat16* __restrict__ Qh, const __nv_bfloat16* __restrict__ Ql,
    const __nv_bfloat16* __restrict__ Kh, const __nv_bfloat16* __restrict__ Kl,
    const __nv_bfloat16* __restrict__ Vh, const __nv_bfloat16* __restrict__ Vl,
    const float* __restrict__ bias,
    __nv_bfloat16* __restrict__ Yh, __nv_bfloat16* __restrict__ Yl)
{
    extern __shared__ char smraw[];
    const uint32_t sQh = smem_u32(smraw);
    const uint32_t sQl = sQh + QT * VSTR;
    const uint32_t sKV = sQl + QT * VSTR;   // 2 stages x {Kh,Kl,Vh,Vl}

    const int h   = blockIdx.x;
    const int qt  = blockIdx.y;
    const int b   = blockIdx.z;
    const int tid = threadIdx.x;
    const int lane = tid & 31;
    const int wq   = tid >> 5;          // 0..7, warp q-row block
    const int q0   = qt * QT;

    const size_t headoff = ((size_t)(b * H_ + h)) * N_ * DK_;
    const __nv_bfloat16* gQh = Qh + headoff + (size_t)q0 * DK_;
    const __nv_bfloat16* gQl = Ql + headoff + (size_t)q0 * DK_;
    const __nv_bfloat16* gKh = Kh + headoff;
    const __nv_bfloat16* gKl = Kl + headoff;
    const __nv_bfloat16* gVh = Vh + headoff;
    const __nv_bfloat16* gVl = Vl + headoff;

    // --- load Q tiles (plain vectorized, once) ---
    #pragma unroll
    for (int t = 0; t < 4; ++t) {
        int idx = tid + t * 256;            // 0..1023
        int row = idx >> 3, c16 = idx & 7;
        uint32_t so = row * VSTR + c16 * 16;
        size_t   go = (size_t)row * DK_ + c16 * 8;
        *(float4*)(smraw + (sQh - smem_u32(smraw)) + so) = *(const float4*)(gQh + go);
        *(float4*)(smraw + (sQl - smem_u32(smraw)) + so) = *(const float4*)(gQl + go);
    }

    // --- issue stage 0 K/V loads ---
    #pragma unroll
    for (int t = 0; t < 8; ++t) {
        int idx = tid + t * 256;
        int tile = idx >> 9;
        int w = idx & 511;
        int row = w >> 3, c16 = w & 7;
        const __nv_bfloat16* src =
            (tile == 0 ? gKh : tile == 1 ? gKl : tile == 2 ? gVh : gVl)
            + (size_t)row * DK_ + c16 * 8;
        CP16(sKV + tile * ATILE + row * VSTR + c16 * 16, src);
    }
    CPCOMMIT();

    __syncthreads();   // Q smem ready

    // --- Q fragments (registers, reused all iterations) ---
    uint32_t qhf[4][4], qlf[4][4];
    #pragma unroll
    for (int ks = 0; ks < 4; ++ks) {
        uint32_t ao = (uint32_t)((wq * 16 + (lane & 15)) * VSTR
                                 + (lane >> 4) * 16 + ks * 32);
        ldmx4(qhf[ks][0], qhf[ks][1], qhf[ks][2], qhf[ks][3], sQh + ao);
        ldmx4(qlf[ks][0], qlf[ks][1], qlf[ks][2], qlf[ks][3], sQl + ao);
    }

    const float* bp0 = bias + ((size_t)b * N_ + q0 + wq * 16 + (lane >> 2)) * N_
                       + (lane & 3) * 2;
    const float* bp1 = bp0 + 8 * (size_t)N_;

    float Oc[8][4];
    #pragma unroll
    for (int j = 0; j < 8; ++j)
        #pragma unroll
        for (int e = 0; e < 4; ++e) Oc[j][e] = 0.0f;
    float m0 = -1e30f, m1 = -1e30f, l0 = 0.0f, l1 = 0.0f;

    for (int kt = 0; kt < 32; ++kt) {
        const int k0 = kt * 64;
        // issue next stage
        if (kt + 1 < 32) {
            uint32_t sb = sKV + (uint32_t)((kt + 1) & 1) * 4 * ATILE;
            int nk0 = k0 + 64;
            #pragma unroll
            for (int t = 0; t < 8; ++t) {
                int idx = tid + t * 256;
                int tile = idx >> 9;
                int w = idx & 511;
                int row = w >> 3, c16 = w & 7;
                const __nv_bfloat16* src =
                    (tile == 0 ? gKh : tile == 1 ? gKl : tile == 2 ? gVh : gVl)
                    + (size_t)(nk0 + row) * DK_ + c16 * 8;
                CP16(sb + tile * ATILE + row * VSTR + c16 * 16, src);
            }
            CPCOMMIT();
            CPWAIT(1);
        } else {
            CPWAIT(0);
        }
        __syncthreads();

        uint32_t st = sKV + (uint32_t)(kt & 1) * 4 * ATILE;
        uint32_t sKh_ = st, sKl_ = st + ATILE, sVh_ = st + 2 * ATILE,
                 sVl_ = st + 3 * ATILE;

        // ---- S = Qh Kh^T + Qh Kl^T + Ql Kh^T ----
        float Sc[8][4];
        #pragma unroll
        for (int j = 0; j < 8; ++j) {
            #pragma unroll
            for (int e = 0; e < 4; ++e) Sc[j][e] = 0.0f;
            uint32_t kh[4][2], kl[4][2];
            #pragma unroll
            for (int kp = 0; kp < 2; ++kp) {
                uint32_t ao = (uint32_t)((j * 8 + (lane & 7)) * VSTR
                                         + kp * 64 + (lane >> 3) * 16);
                uint32_t r0, r1, r2, r3;
                ldmx4(r0, r1, r2, r3, sKh_ + ao);
                kh[2*kp][0] = r0; kh[2*kp][1] = r1;
                kh[2*kp+1][0] = r2; kh[2*kp+1][1] = r3;
                ldmx4(r0, r1, r2, r3, sKl_ + ao);
                kl[2*kp][0] = r0; kl[2*kp][1] = r1;
                kl[2*kp+1][0] = r2; kl[2*kp+1][1] = r3;
            }
            #pragma unroll
            for (int ks = 0; ks < 4; ++ks) {
                mma16816(Sc[j], qhf[ks], kh[ks]);
                mma16816(Sc[j], qhf[ks], kl[ks]);
                mma16816(Sc[j], qlf[ks], kh[ks]);
            }
        }

        // ---- bias + scale ----
        #pragma unroll
        for (int j = 0; j < 8; ++j) {
            float2 bb0 = *(const float2*)(bp0 + k0 + j * 8);
            float2 bb1 = *(const float2*)(bp1 + k0 + j * 8);
            Sc[j][0] = Sc[j][0] * 0.125f + bb0.x;
            Sc[j][1] = Sc[j][1] * 0.125f + bb0.y;
            Sc[j][2] = Sc[j][2] * 0.125f + bb1.x;
            Sc[j][3] = Sc[j][3] * 0.125f + bb1.y;
        }

        // ---- online softmax (rows: lane/4 and lane/4+8) ----
        float mt0 = -1e30f, mt1 = -1e30f;
        #pragma unroll
        for (int j = 0; j < 8; ++j) {
            mt0 = fmaxf(mt0, fmaxf(Sc[j][0], Sc[j][1]));
            mt1 = fmaxf(mt1, fmaxf(Sc[j][2], Sc[j][3]));
        }
        mt0 = fmaxf(mt0, __shfl_xor_sync(0xffffffffu, mt0, 1));
        mt0 = fmaxf(mt0, __shfl_xor_sync(0xffffffffu, mt0, 2));
        mt1 = fmaxf(mt1, __shfl_xor_sync(0xffffffffu, mt1, 1));
        mt1 = fmaxf(mt1, __shfl_xor_sync(0xffffffffu, mt1, 2));
        float mn0 = fmaxf(m0, mt0), mn1 = fmaxf(m1, mt1);
        float cf0 = __expf(m0 - mn0), cf1 = __expf(m1 - mn1);
        m0 = mn0; m1 = mn1;
        float ls0 = 0.0f, ls1 = 0.0f;
        #pragma unroll
        for (int j = 0; j < 8; ++j) {
            Sc[j][0] = __expf(Sc[j][0] - mn0);
            Sc[j][1] = __expf(Sc[j][1] - mn0);
            Sc[j][2] = __expf(Sc[j][2] - mn1);
            Sc[j][3] = __expf(Sc[j][3] - mn1);
            ls0 += Sc[j][0] + Sc[j][1];
            ls1 += Sc[j][2] + Sc[j][3];
        }
        ls0 += __shfl_xor_sync(0xffffffffu, ls0, 1);
        ls0 += __shfl_xor_sync(0xffffffffu, ls0, 2);
        ls1 += __shfl_xor_sync(0xffffffffu, ls1, 1);
        ls1 += __shfl_xor_sync(0xffffffffu, ls1, 2);
        l0 = l0 * cf0 + ls0;
        l1 = l1 * cf1 + ls1;
        #pragma unroll
        for (int j = 0; j < 8; ++j) {
            Oc[j][0] *= cf0; Oc[j][1] *= cf0;
            Oc[j][2] *= cf1; Oc[j][3] *= cf1;
        }

        // ---- P fragments (A-operand layout, split hi/lo) ----
        uint32_t pha[4][4], pla[4][4];
        #pragma unroll
        for (int ks = 0; ks < 4; ++ks) {
            split2(Sc[2*ks][0],   Sc[2*ks][1],   pha[ks][0], pla[ks][0]);
            split2(Sc[2*ks][2],   Sc[2*ks][3],   pha[ks][1], pla[ks][1]);
            split2(Sc[2*ks+1][0], Sc[2*ks+1][1], pha[ks][2], pla[ks][2]);
            split2(Sc[2*ks+1][2], Sc[2*ks+1][3], pha[ks][3], pla[ks][3]);
        }

        // ---- O += P V  (V^T frags via ldmatrix.trans) ----
        #pragma unroll
        for (int jd = 0; jd < 8; ++jd) {
            uint32_t vh[4][2], vl[4][2];
            #pragma unroll
            for (int kp = 0; kp < 2; ++kp) {
                uint32_t ao = (uint32_t)((kp * 32 + lane) * VSTR + jd * 16);
                uint32_t r0, r1, r2, r3;
                ldmx4t(r0, r1, r2, r3, sVh_ + ao);
                vh[2*kp][0] = r0; vh[2*kp][1] = r1;
                vh[2*kp+1][0] = r2; vh[2*kp+1][1] = r3;
                ldmx4t(r0, r1, r2, r3, sVl_ + ao);
                vl[2*kp][0] = r0; vl[2*kp][1] = r1;
                vl[2*kp+1][0] = r2; vl[2*kp+1][1] = r3;
            }
            #pragma unroll
            for (int ks = 0; ks < 4; ++ks) {
                mma16816(Oc[jd], pha[ks], vh[ks]);
                mma16816(Oc[jd], pha[ks], vl[ks]);
                mma16816(Oc[jd], pla[ks], vh[ks]);
            }
        }
        __syncthreads();
    }

    // ---- epilogue: normalize, split, write Yh/Yl head-scattered ----
    float i0 = 1.0f / l0, i1 = 1.0f / l1;
    size_t r0g = ((size_t)b * N_ + q0 + wq * 16 + (lane >> 2)) * D_
                 + h * 64 + (lane & 3) * 2;
    size_t r1g = r0g + 8 * (size_t)D_;
    #pragma unroll
    for (int jd = 0; jd < 8; ++jd) {
        uint32_t uh, ul;
        split2(Oc[jd][0] * i0, Oc[jd][1] * i0, uh, ul);
        *(uint32_t*)(Yh + r0g + jd * 8) = uh;
        *(uint32_t*)(Yl + r0g + jd * 8) = ul;
        split2(Oc[jd][2] * i1, Oc[jd][3] * i1, uh, ul);
        *(uint32_t*)(Yh + r1g + jd * 8) = uh;
        *(uint32_t*)(Yl + r1g + jd * 8) = ul;
    }
}

// ---------------------------------------------------------------------------
extern "C" void kernel_launch(void* const* d_in, const int* in_sizes, int n_in,
                              void* d_out, int out_size)
{
    const float* x     = (const float*)d_in[0];
    const float* alpha = (const float*)d_in[1];
    const float* bias  = (const float*)d_in[2];
    const float* Wq    = (const float*)d_in[3];
    const float* bq    = (const float*)d_in[4];
    const float* Wk    = (const float*)d_in[5];
    const float* bk    = (const float*)d_in[6];
    const float* Wv    = (const float*)d_in[7];
    const float* bv    = (const float*)d_in[8];
    const float* Wo    = (const float*)d_in[9];
    const float* bo    = (const float*)d_in[10];
    float* out = (float*)d_out;

    __nv_bfloat16 *ahp, *alp, *whp, *wlp, *qhp, *qlp, *khp, *klp, *vhp, *vlp;
    cudaGetSymbolAddress((void**)&ahp, g_Ah);
    cudaGetSymbolAddress((void**)&alp, g_Al);
    cudaGetSymbolAddress((void**)&whp, g_Wh);
    cudaGetSymbolAddress((void**)&wlp, g_Wl);
    cudaGetSymbolAddress((void**)&qhp, g_Qh);
    cudaGetSymbolAddress((void**)&qlp, g_Ql);
    cudaGetSymbolAddress((void**)&khp, g_Kh);
    cudaGetSymbolAddress((void**)&klp, g_Kl);
    cudaGetSymbolAddress((void**)&vhp, g_Vh);
    cudaGetSymbolAddress((void**)&vlp, g_Vl);

    const int gemm_smem = 2 * STAGE_B;                       // 81920
    cudaFuncSetAttribute(gemm_mma, cudaFuncAttributeMaxDynamicSharedMemorySize,
                         gemm_smem);
    const int attn_smem = 2 * QT * VSTR + 2 * 4 * ATILE;     // 110592
    cudaFuncSetAttribute(attn_mma, cudaFuncAttributeMaxDynamicSharedMemorySize,
                         attn_smem);

    dim3 blk(256);
    split_kernel<<<4096, blk>>>(x, ahp, alp);
    dim3 gw(32, 32);
    wsplit_kernel<<<gw, blk>>>(Wq, whp + 0 * (size_t)D_ * D_, wlp + 0 * (size_t)D_ * D_);
    wsplit_kernel<<<gw, blk>>>(Wk, whp + 1 * (size_t)D_ * D_, wlp + 1 * (size_t)D_ * D_);
    wsplit_kernel<<<gw, blk>>>(Wv, whp + 2 * (size_t)D_ * D_, wlp + 2 * (size_t)D_ * D_);
    wsplit_kernel<<<gw, blk>>>(Wo, whp + 3 * (size_t)D_ * D_, wlp + 3 * (size_t)D_ * D_);

    dim3 gg(8, 32);
    gemm_mma<<<gg, blk, gemm_smem>>>(ahp, alp,
        whp + 0 * (size_t)D_ * D_, wlp + 0 * (size_t)D_ * D_, bq, alpha,
        nullptr, qhp, qlp, 0);
    gemm_mma<<<gg, blk, gemm_smem>>>(ahp, alp,
        whp + 1 * (size_t)D_ * D_, wlp + 1 * (size_t)D_ * D_, bk, alpha,
        nullptr, khp, klp, 1);
    gemm_mma<<<gg, blk, gemm_smem>>>(ahp, alp,
        whp + 2 * (size_t)D_ * D_, wlp + 2 * (size_t)D_ * D_, bv, alpha,
        nullptr, vhp, vlp, 1);

    attn_mma<<<dim3(H_, N_ / QT, B_), blk, attn_smem>>>(
        qhp, qlp, khp, klp, vhp, vlp, bias, ahp, alp);

    gemm_mma<<<gg, blk, gemm_smem>>>(ahp, alp,
        whp + 3 * (size_t)D_ * D_, wlp + 3 * (size_t)D_ * D_, bo, alpha,
        out, nullptr, nullptr, 2);
}